// round 2
// baseline (speedup 1.0000x reference)
#include <cuda_runtime.h>
#include <cuda_bf16.h>
#include <math.h>

// Problem constants
#define SEQ   4096
#define DM    768
#define NH    12
#define DK    64
#define RANK  8
#define NQKV  (3*DM)          // 2304
#define LORA_SCALE 2.0f       // alpha/rank = 16/8
#define INV_SQRT_DK 0.125f    // 1/sqrt(64)

// ---------------- scratch (no allocs allowed) ----------------
__device__ float g_Wcat[NQKV * DM];                 // fused W_eff for q,k,v  (6.8 MB)
__device__ float g_bcat[NQKV];
__device__ float g_qkv[3 * NH * SEQ * DK];          // [proj][head][s][dk]   (37.7 MB)
__device__ float g_attn[NH * SEQ * DK];             // [head][s][dk]         (12.6 MB)

// ---------------- kernel 1: fold LoRA into base weights ----------------
__global__ __launch_bounds__(256) void fuse_weights_kernel(
    const float* __restrict__ wq, const float* __restrict__ bq,
    const float* __restrict__ wqd, const float* __restrict__ wqu,
    const float* __restrict__ wk, const float* __restrict__ bk,
    const float* __restrict__ wkd, const float* __restrict__ wku,
    const float* __restrict__ wv, const float* __restrict__ bv,
    const float* __restrict__ wvd, const float* __restrict__ wvu)
{
    int idx = blockIdx.x * 256 + threadIdx.x;
    if (idx >= NQKV * DM) return;
    int n = idx / DM;
    int d = idx - n * DM;
    int p = n / DM;           // 0=q 1=k 2=v
    int e = n - p * DM;

    const float *w, *bb, *dn, *up;
    if (p == 0)      { w = wq; bb = bq; dn = wqd; up = wqu; }
    else if (p == 1) { w = wk; bb = bk; dn = wkd; up = wku; }
    else             { w = wv; bb = bv; dn = wvd; up = wvu; }

    float acc = 0.f;
#pragma unroll
    for (int r = 0; r < RANK; r++)
        acc += up[e * RANK + r] * dn[r * DM + d];

    g_Wcat[idx] = w[e * DM + d] + LORA_SCALE * acc;
    if (d == 0) g_bcat[n] = bb[e];
}

// ---------------- kernel 2: QKV GEMM  C[s,n] = x @ Wcat^T + bcat ----------------
// 64x64 tile, BK=16, 256 threads, 4x4 per thread. Output scattered to [p][h][s][dk].
__global__ __launch_bounds__(256) void gemm_qkv_kernel(const float* __restrict__ x)
{
    __shared__ float As[16][64];
    __shared__ float Bs[16][64];

    const int n0 = blockIdx.x * 64;
    const int m0 = blockIdx.y * 64;
    const int tid = threadIdx.x;
    const int tx = tid & 15;          // 0..15 -> output col group
    const int ty = tid >> 4;          // 0..15 -> output row group
    const int lr = tid >> 2;          // 0..63 load row
    const int lc = tid & 3;           // 0..3  load float4 col

    float acc[4][4];
#pragma unroll
    for (int i = 0; i < 4; i++)
#pragma unroll
        for (int j = 0; j < 4; j++) acc[i][j] = 0.f;

    for (int k0 = 0; k0 < DM; k0 += 16) {
        float4 a4 = *(const float4*)(x      + (size_t)(m0 + lr) * DM + k0 + lc * 4);
        float4 b4 = *(const float4*)(g_Wcat + (size_t)(n0 + lr) * DM + k0 + lc * 4);
        As[lc*4+0][lr] = a4.x; As[lc*4+1][lr] = a4.y; As[lc*4+2][lr] = a4.z; As[lc*4+3][lr] = a4.w;
        Bs[lc*4+0][lr] = b4.x; Bs[lc*4+1][lr] = b4.y; Bs[lc*4+2][lr] = b4.z; Bs[lc*4+3][lr] = b4.w;
        __syncthreads();
#pragma unroll
        for (int k = 0; k < 16; k++) {
            float ra[4], rb[4];
            *(float4*)ra = *(const float4*)&As[k][ty * 4];
            *(float4*)rb = *(const float4*)&Bs[k][tx * 4];
#pragma unroll
            for (int i = 0; i < 4; i++)
#pragma unroll
                for (int j = 0; j < 4; j++) acc[i][j] += ra[i] * rb[j];
        }
        __syncthreads();
    }

#pragma unroll
    for (int i = 0; i < 4; i++) {
        int m = m0 + ty * 4 + i;
#pragma unroll
        for (int j = 0; j < 4; j++) {
            int n = n0 + tx * 4 + j;
            int p = n / DM;
            int rem = n - p * DM;
            int h = rem >> 6;
            int dd = rem & 63;
            g_qkv[(((size_t)p * NH + h) * SEQ + m) * DK + dd] = acc[i][j] + g_bcat[n];
        }
    }
}

// ---------------- kernel 3: flash attention ----------------
// One thread per Q row. 128 rows per block. K/V tiles of 32x64 in shared.
__global__ __launch_bounds__(128) void flash_kernel()
{
    const int h   = blockIdx.y;
    const int row = blockIdx.x * 128 + threadIdx.x;

    const float* Qp = g_qkv + ((size_t)h * SEQ + row) * DK;
    const float* Kp = g_qkv + ((size_t)(NH + h) * SEQ) * DK;
    const float* Vp = g_qkv + ((size_t)(2 * NH + h) * SEQ) * DK;

    __shared__ float Ks[32][64];
    __shared__ float Vs[32][64];

    float q[64], o[64];
#pragma unroll
    for (int i = 0; i < 16; i++) {
        float4 v4 = ((const float4*)Qp)[i];
        q[4*i] = v4.x; q[4*i+1] = v4.y; q[4*i+2] = v4.z; q[4*i+3] = v4.w;
        o[4*i] = 0.f;  o[4*i+1] = 0.f;  o[4*i+2] = 0.f;  o[4*i+3] = 0.f;
    }
    float m = -1e30f, l = 0.f;

    for (int kb = 0; kb < SEQ; kb += 32) {
        const float4* K4 = (const float4*)(Kp + (size_t)kb * DK);
        const float4* V4 = (const float4*)(Vp + (size_t)kb * DK);
        float4* Ks4 = (float4*)&Ks[0][0];
        float4* Vs4 = (float4*)&Vs[0][0];
#pragma unroll
        for (int i = 0; i < 4; i++) {
            Ks4[threadIdx.x + i * 128] = K4[threadIdx.x + i * 128];
            Vs4[threadIdx.x + i * 128] = V4[threadIdx.x + i * 128];
        }
        __syncthreads();

        for (int g = 0; g < 4; g++) {              // rolled: keeps code in I$
            float s[8];
#pragma unroll
            for (int kk = 0; kk < 8; kk++) {
                const float* kr = &Ks[g * 8 + kk][0];
                float acc = 0.f;
#pragma unroll
                for (int d = 0; d < 64; d++) acc += q[d] * kr[d];
                s[kk] = acc * INV_SQRT_DK;
            }
            float mt = s[0];
#pragma unroll
            for (int kk = 1; kk < 8; kk++) mt = fmaxf(mt, s[kk]);
            float mnew = fmaxf(m, mt);
            float corr = __expf(m - mnew);
            m = mnew;
            l *= corr;
#pragma unroll
            for (int d = 0; d < 64; d++) o[d] *= corr;
#pragma unroll
            for (int kk = 0; kk < 8; kk++) {
                float p = __expf(s[kk] - m);
                l += p;
                const float* vr = &Vs[g * 8 + kk][0];
#pragma unroll
                for (int d = 0; d < 64; d++) o[d] += p * vr[d];
            }
        }
        __syncthreads();
    }

    float inv = 1.f / l;
    float* Op = g_attn + ((size_t)h * SEQ + row) * DK;
#pragma unroll
    for (int i = 0; i < 16; i++) {
        float4 v4;
        v4.x = o[4*i]   * inv; v4.y = o[4*i+1] * inv;
        v4.z = o[4*i+2] * inv; v4.w = o[4*i+3] * inv;
        ((float4*)Op)[i] = v4;
    }
}

// ---------------- kernel 4: output projection ----------------
// out[s,e] = sum_c attn[s,c] * wo[e,c] + bo[e]; attn gathered from [h][s][dk].
__global__ __launch_bounds__(256) void gemm_out_kernel(
    const float* __restrict__ wo, const float* __restrict__ bo,
    float* __restrict__ out)
{
    __shared__ float As[16][64];
    __shared__ float Bs[16][64];

    const int n0 = blockIdx.x * 64;
    const int m0 = blockIdx.y * 64;
    const int tid = threadIdx.x;
    const int tx = tid & 15;
    const int ty = tid >> 4;
    const int lr = tid >> 2;
    const int lc = tid & 3;

    float acc[4][4];
#pragma unroll
    for (int i = 0; i < 4; i++)
#pragma unroll
        for (int j = 0; j < 4; j++) acc[i][j] = 0.f;

    for (int k0 = 0; k0 < DM; k0 += 16) {
        int c = k0 + lc * 4;             // channel index, float4 stays in one head
        int hh = c >> 6;
        int off = c & 63;
        float4 a4 = *(const float4*)(g_attn + ((size_t)hh * SEQ + (m0 + lr)) * DK + off);
        float4 b4 = *(const float4*)(wo + (size_t)(n0 + lr) * DM + k0 + lc * 4);
        As[lc*4+0][lr] = a4.x; As[lc*4+1][lr] = a4.y; As[lc*4+2][lr] = a4.z; As[lc*4+3][lr] = a4.w;
        Bs[lc*4+0][lr] = b4.x; Bs[lc*4+1][lr] = b4.y; Bs[lc*4+2][lr] = b4.z; Bs[lc*4+3][lr] = b4.w;
        __syncthreads();
#pragma unroll
        for (int k = 0; k < 16; k++) {
            float ra[4], rb[4];
            *(float4*)ra = *(const float4*)&As[k][ty * 4];
            *(float4*)rb = *(const float4*)&Bs[k][tx * 4];
#pragma unroll
            for (int i = 0; i < 4; i++)
#pragma unroll
                for (int j = 0; j < 4; j++) acc[i][j] += ra[i] * rb[j];
        }
        __syncthreads();
    }

#pragma unroll
    for (int i = 0; i < 4; i++) {
        int mrow = m0 + ty * 4 + i;
#pragma unroll
        for (int j = 0; j < 4; j++) {
            int n = n0 + tx * 4 + j;
            out[(size_t)mrow * DM + n] = acc[i][j] + bo[n];
        }
    }
}

// ---------------- launch ----------------
extern "C" void kernel_launch(void* const* d_in, const int* in_sizes, int n_in,
                              void* d_out, int out_size)
{
    const float* x   = (const float*)d_in[0];
    const float* wq  = (const float*)d_in[1];
    const float* bq  = (const float*)d_in[2];
    const float* wk  = (const float*)d_in[3];
    const float* bk  = (const float*)d_in[4];
    const float* wv  = (const float*)d_in[5];
    const float* bv  = (const float*)d_in[6];
    const float* wo  = (const float*)d_in[7];
    const float* bo  = (const float*)d_in[8];
    const float* wqd = (const float*)d_in[9];
    const float* wqu = (const float*)d_in[10];
    const float* wkd = (const float*)d_in[11];
    const float* wku = (const float*)d_in[12];
    const float* wvd = (const float*)d_in[13];
    const float* wvu = (const float*)d_in[14];
    float* out = (float*)d_out;

    // 1) fold LoRA into base weights
    {
        int total = NQKV * DM;
        fuse_weights_kernel<<<(total + 255) / 256, 256>>>(
            wq, bq, wqd, wqu, wk, bk, wkd, wku, wv, bv, wvd, wvu);
    }
    // 2) fused QKV projection
    {
        dim3 grid(NQKV / 64, SEQ / 64);
        gemm_qkv_kernel<<<grid, 256>>>(x);
    }
    // 3) flash attention
    {
        dim3 grid(SEQ / 128, NH);
        flash_kernel<<<grid, 128>>>();
    }
    // 4) output projection
    {
        dim3 grid(DM / 64, SEQ / 64);
        gemm_out_kernel<<<grid, 256>>>(wo, bo, out);
    }
}

// round 5
// speedup vs baseline: 2.5073x; 2.5073x over previous
#include <cuda_runtime.h>
#include <cuda_bf16.h>
#include <math.h>
#include <stdint.h>

#define SEQ   4096
#define DM    768
#define NH    12
#define DK    64
#define RANK  8
#define NQKV  (3*DM)
#define LORA_SCALE 2.0f
#define INV_SQRT_DK 0.125f

// ---------------- scratch ----------------
__device__ float g_Wcat[NQKV * DM];
__device__ float g_bcat[NQKV];
__device__ float g_qkv[3 * NH * SEQ * DK];   // [p][h][s][dk]
__device__ float g_attn[NH * SEQ * DK];      // [h][s][dk]

// ---------------- helpers ----------------
__device__ __forceinline__ uint32_t f2tf32(float x) {
    uint32_t u;
    asm("cvt.rna.tf32.f32 %0, %1;" : "=r"(u) : "f"(x));
    return u;
}

__device__ __forceinline__ void mma_tf32(float* d, const uint32_t* a, uint32_t b0, uint32_t b1) {
    asm volatile(
        "mma.sync.aligned.m16n8k8.row.col.f32.tf32.tf32.f32 "
        "{%0,%1,%2,%3}, {%4,%5,%6,%7}, {%8,%9}, {%0,%1,%2,%3};"
        : "+f"(d[0]), "+f"(d[1]), "+f"(d[2]), "+f"(d[3])
        : "r"(a[0]), "r"(a[1]), "r"(a[2]), "r"(a[3]), "r"(b0), "r"(b1));
}

__device__ __forceinline__ uint32_t ldu(const float* p) { return __float_as_uint(*p); }

// ---------------- kernel 1: fold LoRA ----------------
__global__ __launch_bounds__(256) void fuse_weights_kernel(
    const float* __restrict__ wq, const float* __restrict__ bq,
    const float* __restrict__ wqd, const float* __restrict__ wqu,
    const float* __restrict__ wk, const float* __restrict__ bk,
    const float* __restrict__ wkd, const float* __restrict__ wku,
    const float* __restrict__ wv, const float* __restrict__ bv,
    const float* __restrict__ wvd, const float* __restrict__ wvu)
{
    int idx = blockIdx.x * 256 + threadIdx.x;
    if (idx >= NQKV * DM) return;
    int n = idx / DM;
    int d = idx - n * DM;
    int p = n / DM;
    int e = n - p * DM;
    const float *w, *bb, *dn, *up;
    if (p == 0)      { w = wq; bb = bq; dn = wqd; up = wqu; }
    else if (p == 1) { w = wk; bb = bk; dn = wkd; up = wku; }
    else             { w = wv; bb = bv; dn = wvd; up = wvu; }
    float acc = 0.f;
#pragma unroll
    for (int r = 0; r < RANK; r++)
        acc += up[e * RANK + r] * dn[r * DM + d];
    g_Wcat[idx] = w[e * DM + d] + LORA_SCALE * acc;
    if (d == 0) g_bcat[n] = bb[e];
}

// ---------------- kernel 2: QKV GEMM, 3xTF32 ----------------
// C[m,n] = x[m,:] . Wcat[n,:] + bcat[n], scattered to g_qkv[p][h][s][dk]
// BM=64, BN=64, BK=16, 128 threads, warp tile 32x32.
__global__ __launch_bounds__(128) void gemm_qkv_tc(const float* __restrict__ x)
{
    __shared__ float Ah[64][20], Al[64][20], Bh[64][20], Bl[64][20];

    const int n0 = blockIdx.x * 64;
    const int m0 = blockIdx.y * 64;
    const int tid = threadIdx.x;
    const int w   = tid >> 5;
    const int lane = tid & 31;
    const int g   = lane >> 2;
    const int tg  = lane & 3;
    const int wm = (w & 1) * 32;
    const int wn = (w >> 1) * 32;

    float acc[2][4][4];
#pragma unroll
    for (int mt = 0; mt < 2; mt++)
#pragma unroll
        for (int nt = 0; nt < 4; nt++)
#pragma unroll
            for (int i = 0; i < 4; i++) acc[mt][nt][i] = 0.f;

    for (int k0 = 0; k0 < DM; k0 += 16) {
#pragma unroll
        for (int i = 0; i < 2; i++) {
            int id = tid + 128 * i;
            int row = id >> 2;
            int c4  = (id & 3) * 4;
            float4 a4 = *(const float4*)(x + (size_t)(m0 + row) * DM + k0 + c4);
            float4 b4 = *(const float4*)(g_Wcat + (size_t)(n0 + row) * DM + k0 + c4);
            float4 ah, al, bh, bl;
            ah.x = __uint_as_float(f2tf32(a4.x)); al.x = __uint_as_float(f2tf32(a4.x - ah.x));
            ah.y = __uint_as_float(f2tf32(a4.y)); al.y = __uint_as_float(f2tf32(a4.y - ah.y));
            ah.z = __uint_as_float(f2tf32(a4.z)); al.z = __uint_as_float(f2tf32(a4.z - ah.z));
            ah.w = __uint_as_float(f2tf32(a4.w)); al.w = __uint_as_float(f2tf32(a4.w - ah.w));
            bh.x = __uint_as_float(f2tf32(b4.x)); bl.x = __uint_as_float(f2tf32(b4.x - bh.x));
            bh.y = __uint_as_float(f2tf32(b4.y)); bl.y = __uint_as_float(f2tf32(b4.y - bh.y));
            bh.z = __uint_as_float(f2tf32(b4.z)); bl.z = __uint_as_float(f2tf32(b4.z - bh.z));
            bh.w = __uint_as_float(f2tf32(b4.w)); bl.w = __uint_as_float(f2tf32(b4.w - bh.w));
            *(float4*)&Ah[row][c4] = ah; *(float4*)&Al[row][c4] = al;
            *(float4*)&Bh[row][c4] = bh; *(float4*)&Bl[row][c4] = bl;
        }
        __syncthreads();

#pragma unroll
        for (int ks = 0; ks < 2; ks++) {
            const int kc = 8 * ks;
            uint32_t afh[2][4], afl[2][4];
#pragma unroll
            for (int mt = 0; mt < 2; mt++) {
                int r = wm + 16 * mt;
                afh[mt][0] = ldu(&Ah[r + g][kc + tg]);
                afh[mt][1] = ldu(&Ah[r + g + 8][kc + tg]);
                afh[mt][2] = ldu(&Ah[r + g][kc + tg + 4]);
                afh[mt][3] = ldu(&Ah[r + g + 8][kc + tg + 4]);
                afl[mt][0] = ldu(&Al[r + g][kc + tg]);
                afl[mt][1] = ldu(&Al[r + g + 8][kc + tg]);
                afl[mt][2] = ldu(&Al[r + g][kc + tg + 4]);
                afl[mt][3] = ldu(&Al[r + g + 8][kc + tg + 4]);
            }
            uint32_t bfh[4][2], bfl[4][2];
#pragma unroll
            for (int nt = 0; nt < 4; nt++) {
                int r = wn + 8 * nt + g;
                bfh[nt][0] = ldu(&Bh[r][kc + tg]);
                bfh[nt][1] = ldu(&Bh[r][kc + tg + 4]);
                bfl[nt][0] = ldu(&Bl[r][kc + tg]);
                bfl[nt][1] = ldu(&Bl[r][kc + tg + 4]);
            }
#pragma unroll
            for (int mt = 0; mt < 2; mt++)
#pragma unroll
                for (int nt = 0; nt < 4; nt++) {
                    mma_tf32(acc[mt][nt], afh[mt], bfh[nt][0], bfh[nt][1]);
                    mma_tf32(acc[mt][nt], afh[mt], bfl[nt][0], bfl[nt][1]);
                    mma_tf32(acc[mt][nt], afl[mt], bfh[nt][0], bfh[nt][1]);
                }
        }
        __syncthreads();
    }

    // epilogue: scatter
#pragma unroll
    for (int mt = 0; mt < 2; mt++)
#pragma unroll
        for (int nt = 0; nt < 4; nt++) {
            int rowA = m0 + wm + 16 * mt + g;
            int colA = n0 + wn + 8 * nt + 2 * tg;
#pragma unroll
            for (int half = 0; half < 2; half++) {
                int mrow = rowA + half * 8;
#pragma unroll
                for (int j = 0; j < 2; j++) {
                    int n = colA + j;
                    int p = n / DM;
                    int rem = n - p * DM;
                    int h = rem >> 6;
                    int dd = rem & 63;
                    g_qkv[(((size_t)p * NH + h) * SEQ + mrow) * DK + dd] =
                        acc[mt][nt][half * 2 + j] + g_bcat[n];
                }
            }
        }
}

// ---------------- kernel 3: flash attention, tf32 tensor cores ----------------
// block: 128 threads (4 warps), 64 q-rows (16 per warp). Key tiles of 32.
__global__ __launch_bounds__(128) void flash_tc()
{
    __shared__ float Ks[32][68];
    __shared__ float Vh[32][72];
    __shared__ float Vl[32][72];
    __shared__ float Ps[64][36];

    const int h  = blockIdx.y;
    const int m0 = blockIdx.x * 64;
    const int tid = threadIdx.x;
    const int w = tid >> 5;
    const int lane = tid & 31;
    const int g  = lane >> 2;
    const int tg = lane & 3;

    const float* Qp = g_qkv + (size_t)h * SEQ * DK;
    const float* Kp = g_qkv + (size_t)(NH + h) * SEQ * DK;
    const float* Vp = g_qkv + (size_t)(2 * NH + h) * SEQ * DK;

    const int r0 = m0 + 16 * w + g;      // warp-local rows r0, r0+8

    // Q fragments (scaled by 1/sqrt(dk)), 8 k-subchunks
    uint32_t qa[8][4];
#pragma unroll
    for (int ks = 0; ks < 8; ks++) {
        int c = 8 * ks + tg;
        qa[ks][0] = f2tf32(Qp[(size_t)r0 * DK + c] * INV_SQRT_DK);
        qa[ks][1] = f2tf32(Qp[(size_t)(r0 + 8) * DK + c] * INV_SQRT_DK);
        qa[ks][2] = f2tf32(Qp[(size_t)r0 * DK + c + 4] * INV_SQRT_DK);
        qa[ks][3] = f2tf32(Qp[(size_t)(r0 + 8) * DK + c + 4] * INV_SQRT_DK);
    }

    float oacc[8][4];
#pragma unroll
    for (int dt = 0; dt < 8; dt++)
#pragma unroll
        for (int i = 0; i < 4; i++) oacc[dt][i] = 0.f;
    float m0_ = -1e30f, m1_ = -1e30f, l0 = 0.f, l1 = 0.f;

    for (int kb = 0; kb < SEQ; kb += 32) {
        // cooperative load K (tf32) and V (hi/lo split)
#pragma unroll
        for (int i = 0; i < 4; i++) {
            int id = tid + 128 * i;          // 512 float4s
            int row = id >> 4;
            int c4  = (id & 15) * 4;
            float4 kv = *(const float4*)(Kp + (size_t)(kb + row) * DK + c4);
            float4 vv = *(const float4*)(Vp + (size_t)(kb + row) * DK + c4);
            float4 kt, vh, vl;
            kt.x = __uint_as_float(f2tf32(kv.x)); kt.y = __uint_as_float(f2tf32(kv.y));
            kt.z = __uint_as_float(f2tf32(kv.z)); kt.w = __uint_as_float(f2tf32(kv.w));
            vh.x = __uint_as_float(f2tf32(vv.x)); vl.x = __uint_as_float(f2tf32(vv.x - vh.x));
            vh.y = __uint_as_float(f2tf32(vv.y)); vl.y = __uint_as_float(f2tf32(vv.y - vh.y));
            vh.z = __uint_as_float(f2tf32(vv.z)); vl.z = __uint_as_float(f2tf32(vv.z - vh.z));
            vh.w = __uint_as_float(f2tf32(vv.w)); vl.w = __uint_as_float(f2tf32(vv.w - vh.w));
            *(float4*)&Ks[row][c4] = kt;
            *(float4*)&Vh[row][c4] = vh;
            *(float4*)&Vl[row][c4] = vl;
        }
        __syncthreads();

        // S = Q . K^T  (64x32 per block; 16x32 per warp)
        float sacc[4][4];
#pragma unroll
        for (int nt = 0; nt < 4; nt++)
#pragma unroll
            for (int i = 0; i < 4; i++) sacc[nt][i] = 0.f;
#pragma unroll
        for (int nt = 0; nt < 4; nt++) {
            int key = 8 * nt + g;
#pragma unroll
            for (int ks = 0; ks < 8; ks++) {
                uint32_t b0 = ldu(&Ks[key][8 * ks + tg]);
                uint32_t b1 = ldu(&Ks[key][8 * ks + tg + 4]);
                mma_tf32(sacc[nt], qa[ks], b0, b1);
            }
        }

        // online softmax (two row groups per lane)
        float tmax0 = -1e30f, tmax1 = -1e30f;
#pragma unroll
        for (int nt = 0; nt < 4; nt++) {
            tmax0 = fmaxf(tmax0, fmaxf(sacc[nt][0], sacc[nt][1]));
            tmax1 = fmaxf(tmax1, fmaxf(sacc[nt][2], sacc[nt][3]));
        }
        tmax0 = fmaxf(tmax0, __shfl_xor_sync(0xffffffff, tmax0, 1));
        tmax0 = fmaxf(tmax0, __shfl_xor_sync(0xffffffff, tmax0, 2));
        tmax1 = fmaxf(tmax1, __shfl_xor_sync(0xffffffff, tmax1, 1));
        tmax1 = fmaxf(tmax1, __shfl_xor_sync(0xffffffff, tmax1, 2));

        float mn0 = fmaxf(m0_, tmax0);
        float mn1 = fmaxf(m1_, tmax1);
        float corr0 = __expf(m0_ - mn0);
        float corr1 = __expf(m1_ - mn1);
        m0_ = mn0; m1_ = mn1;

        float rs0 = 0.f, rs1 = 0.f;
#pragma unroll
        for (int nt = 0; nt < 4; nt++) {
            sacc[nt][0] = __expf(sacc[nt][0] - m0_);
            sacc[nt][1] = __expf(sacc[nt][1] - m0_);
            sacc[nt][2] = __expf(sacc[nt][2] - m1_);
            sacc[nt][3] = __expf(sacc[nt][3] - m1_);
            rs0 += sacc[nt][0] + sacc[nt][1];
            rs1 += sacc[nt][2] + sacc[nt][3];
        }
        rs0 += __shfl_xor_sync(0xffffffff, rs0, 1);
        rs0 += __shfl_xor_sync(0xffffffff, rs0, 2);
        rs1 += __shfl_xor_sync(0xffffffff, rs1, 1);
        rs1 += __shfl_xor_sync(0xffffffff, rs1, 2);
        l0 = l0 * corr0 + rs0;
        l1 = l1 * corr1 + rs1;

        // rescale O
#pragma unroll
        for (int dt = 0; dt < 8; dt++) {
            oacc[dt][0] *= corr0; oacc[dt][1] *= corr0;
            oacc[dt][2] *= corr1; oacc[dt][3] *= corr1;
        }

        // write P (tf32) to smem (warp-private rows)
        {
            int pr = 16 * w + g;
#pragma unroll
            for (int nt = 0; nt < 4; nt++) {
                int pc = 8 * nt + 2 * tg;
                float2 p01, p23;
                p01.x = __uint_as_float(f2tf32(sacc[nt][0]));
                p01.y = __uint_as_float(f2tf32(sacc[nt][1]));
                p23.x = __uint_as_float(f2tf32(sacc[nt][2]));
                p23.y = __uint_as_float(f2tf32(sacc[nt][3]));
                *(float2*)&Ps[pr][pc]     = p01;
                *(float2*)&Ps[pr + 8][pc] = p23;
            }
        }
        __syncwarp();

        // O += P . Vh + P . Vl
#pragma unroll
        for (int ks = 0; ks < 4; ks++) {
            int pr = 16 * w;
            uint32_t pa[4];
            pa[0] = ldu(&Ps[pr + g][8 * ks + tg]);
            pa[1] = ldu(&Ps[pr + g + 8][8 * ks + tg]);
            pa[2] = ldu(&Ps[pr + g][8 * ks + tg + 4]);
            pa[3] = ldu(&Ps[pr + g + 8][8 * ks + tg + 4]);
#pragma unroll
            for (int dt = 0; dt < 8; dt++) {
                int d = 8 * dt + g;
                uint32_t bh0 = ldu(&Vh[8 * ks + tg][d]);
                uint32_t bh1 = ldu(&Vh[8 * ks + tg + 4][d]);
                uint32_t bl0 = ldu(&Vl[8 * ks + tg][d]);
                uint32_t bl1 = ldu(&Vl[8 * ks + tg + 4][d]);
                mma_tf32(oacc[dt], pa, bh0, bh1);
                mma_tf32(oacc[dt], pa, bl0, bl1);
            }
        }
        __syncthreads();
    }

    // epilogue
    float inv0 = 1.f / l0;
    float inv1 = 1.f / l1;
    float* Op = g_attn + (size_t)h * SEQ * DK;
#pragma unroll
    for (int dt = 0; dt < 8; dt++) {
        int c = 8 * dt + 2 * tg;
        float2 v01, v23;
        v01.x = oacc[dt][0] * inv0; v01.y = oacc[dt][1] * inv0;
        v23.x = oacc[dt][2] * inv1; v23.y = oacc[dt][3] * inv1;
        *(float2*)(Op + (size_t)r0 * DK + c)       = v01;
        *(float2*)(Op + (size_t)(r0 + 8) * DK + c) = v23;
    }
}

// ---------------- kernel 4: output projection, 3xTF32 ----------------
__global__ __launch_bounds__(128) void gemm_out_tc(
    const float* __restrict__ wo, const float* __restrict__ bo,
    float* __restrict__ out)
{
    __shared__ float Ah[64][20], Al[64][20], Bh[64][20], Bl[64][20];

    const int n0 = blockIdx.x * 64;
    const int m0 = blockIdx.y * 64;
    const int tid = threadIdx.x;
    const int w   = tid >> 5;
    const int lane = tid & 31;
    const int g   = lane >> 2;
    const int tg  = lane & 3;
    const int wm = (w & 1) * 32;
    const int wn = (w >> 1) * 32;

    float acc[2][4][4];
#pragma unroll
    for (int mt = 0; mt < 2; mt++)
#pragma unroll
        for (int nt = 0; nt < 4; nt++)
#pragma unroll
            for (int i = 0; i < 4; i++) acc[mt][nt][i] = 0.f;

    for (int k0 = 0; k0 < DM; k0 += 16) {
#pragma unroll
        for (int i = 0; i < 2; i++) {
            int id = tid + 128 * i;
            int row = id >> 2;
            int c4  = (id & 3) * 4;
            int c = k0 + c4;
            int hh = c >> 6;
            int off = c & 63;
            float4 a4 = *(const float4*)(g_attn + ((size_t)hh * SEQ + (m0 + row)) * DK + off);
            float4 b4 = *(const float4*)(wo + (size_t)(n0 + row) * DM + c);
            float4 ah, al, bh, bl;
            ah.x = __uint_as_float(f2tf32(a4.x)); al.x = __uint_as_float(f2tf32(a4.x - ah.x));
            ah.y = __uint_as_float(f2tf32(a4.y)); al.y = __uint_as_float(f2tf32(a4.y - ah.y));
            ah.z = __uint_as_float(f2tf32(a4.z)); al.z = __uint_as_float(f2tf32(a4.z - ah.z));
            ah.w = __uint_as_float(f2tf32(a4.w)); al.w = __uint_as_float(f2tf32(a4.w - ah.w));
            bh.x = __uint_as_float(f2tf32(b4.x)); bl.x = __uint_as_float(f2tf32(b4.x - bh.x));
            bh.y = __uint_as_float(f2tf32(b4.y)); bl.y = __uint_as_float(f2tf32(b4.y - bh.y));
            bh.z = __uint_as_float(f2tf32(b4.z)); bl.z = __uint_as_float(f2tf32(b4.z - bh.z));
            bh.w = __uint_as_float(f2tf32(b4.w)); bl.w = __uint_as_float(f2tf32(b4.w - bh.w));
            *(float4*)&Ah[row][c4] = ah; *(float4*)&Al[row][c4] = al;
            *(float4*)&Bh[row][c4] = bh; *(float4*)&Bl[row][c4] = bl;
        }
        __syncthreads();

#pragma unroll
        for (int ks = 0; ks < 2; ks++) {
            const int kc = 8 * ks;
            uint32_t afh[2][4], afl[2][4];
#pragma unroll
            for (int mt = 0; mt < 2; mt++) {
                int r = wm + 16 * mt;
                afh[mt][0] = ldu(&Ah[r + g][kc + tg]);
                afh[mt][1] = ldu(&Ah[r + g + 8][kc + tg]);
                afh[mt][2] = ldu(&Ah[r + g][kc + tg + 4]);
                afh[mt][3] = ldu(&Ah[r + g + 8][kc + tg + 4]);
                afl[mt][0] = ldu(&Al[r + g][kc + tg]);
                afl[mt][1] = ldu(&Al[r + g + 8][kc + tg]);
                afl[mt][2] = ldu(&Al[r + g][kc + tg + 4]);
                afl[mt][3] = ldu(&Al[r + g + 8][kc + tg + 4]);
            }
            uint32_t bfh[4][2], bfl[4][2];
#pragma unroll
            for (int nt = 0; nt < 4; nt++) {
                int r = wn + 8 * nt + g;
                bfh[nt][0] = ldu(&Bh[r][kc + tg]);
                bfh[nt][1] = ldu(&Bh[r][kc + tg + 4]);
                bfl[nt][0] = ldu(&Bl[r][kc + tg]);
                bfl[nt][1] = ldu(&Bl[r][kc + tg + 4]);
            }
#pragma unroll
            for (int mt = 0; mt < 2; mt++)
#pragma unroll
                for (int nt = 0; nt < 4; nt++) {
                    mma_tf32(acc[mt][nt], afh[mt], bfh[nt][0], bfh[nt][1]);
                    mma_tf32(acc[mt][nt], afh[mt], bfl[nt][0], bfl[nt][1]);
                    mma_tf32(acc[mt][nt], afl[mt], bfh[nt][0], bfh[nt][1]);
                }
        }
        __syncthreads();
    }

#pragma unroll
    for (int mt = 0; mt < 2; mt++)
#pragma unroll
        for (int nt = 0; nt < 4; nt++) {
            int rowA = m0 + wm + 16 * mt + g;
            int colA = n0 + wn + 8 * nt + 2 * tg;
#pragma unroll
            for (int half = 0; half < 2; half++) {
                int mrow = rowA + half * 8;
                out[(size_t)mrow * DM + colA]     = acc[mt][nt][half * 2]     + bo[colA];
                out[(size_t)mrow * DM + colA + 1] = acc[mt][nt][half * 2 + 1] + bo[colA + 1];
            }
        }
}

// ---------------- launch ----------------
extern "C" void kernel_launch(void* const* d_in, const int* in_sizes, int n_in,
                              void* d_out, int out_size)
{
    const float* x   = (const float*)d_in[0];
    const float* wq  = (const float*)d_in[1];
    const float* bq  = (const float*)d_in[2];
    const float* wk  = (const float*)d_in[3];
    const float* bk  = (const float*)d_in[4];
    const float* wv  = (const float*)d_in[5];
    const float* bv  = (const float*)d_in[6];
    const float* wo  = (const float*)d_in[7];
    const float* bo  = (const float*)d_in[8];
    const float* wqd = (const float*)d_in[9];
    const float* wqu = (const float*)d_in[10];
    const float* wkd = (const float*)d_in[11];
    const float* wku = (const float*)d_in[12];
    const float* wvd = (const float*)d_in[13];
    const float* wvu = (const float*)d_in[14];
    float* out = (float*)d_out;

    {
        int total = NQKV * DM;
        fuse_weights_kernel<<<(total + 255) / 256, 256>>>(
            wq, bq, wqd, wqu, wk, bk, wkd, wku, wv, bv, wvd, wvu);
    }
    {
        dim3 grid(NQKV / 64, SEQ / 64);
        gemm_qkv_tc<<<grid, 128>>>(x);
    }
    {
        dim3 grid(SEQ / 64, NH);
        flash_tc<<<grid, 128>>>();
    }
    {
        dim3 grid(DM / 64, SEQ / 64);
        gemm_out_tc<<<grid, 128>>>(wo, bo, out);
    }
}

// round 7
// speedup vs baseline: 3.5804x; 1.4280x over previous
#include <cuda_runtime.h>
#include <cuda_bf16.h>
#include <math.h>
#include <stdint.h>

#define SEQ   4096
#define DM    768
#define NH    12
#define DK    64
#define RANK  8
#define NQKV  (3*DM)
#define LORA_SCALE 2.0f
#define INV_SQRT_DK 0.125f

// ---------------- scratch ----------------
__device__ float g_Wcat[NQKV * DM];
__device__ float g_bcat[NQKV];
__device__ float g_qkv[3 * NH * SEQ * DK];   // [p][h][s][dk]
__device__ float g_attn[NH * SEQ * DK];      // [h][s][dk]

// ---------------- helpers ----------------
__device__ __forceinline__ uint32_t f2tf32(float x) {
    uint32_t u;
    asm("cvt.rna.tf32.f32 %0, %1;" : "=r"(u) : "f"(x));
    return u;
}

__device__ __forceinline__ void mma_tf32(float* d, const uint32_t* a, uint32_t b0, uint32_t b1) {
    asm volatile(
        "mma.sync.aligned.m16n8k8.row.col.f32.tf32.tf32.f32 "
        "{%0,%1,%2,%3}, {%4,%5,%6,%7}, {%8,%9}, {%0,%1,%2,%3};"
        : "+f"(d[0]), "+f"(d[1]), "+f"(d[2]), "+f"(d[3])
        : "r"(a[0]), "r"(a[1]), "r"(a[2]), "r"(a[3]), "r"(b0), "r"(b1));
}

__device__ __forceinline__ uint32_t ldu(const float* p) { return __float_as_uint(*p); }

// ---------------- kernel 1: fold LoRA ----------------
__global__ __launch_bounds__(256) void fuse_weights_kernel(
    const float* __restrict__ wq, const float* __restrict__ bq,
    const float* __restrict__ wqd, const float* __restrict__ wqu,
    const float* __restrict__ wk, const float* __restrict__ bk,
    const float* __restrict__ wkd, const float* __restrict__ wku,
    const float* __restrict__ wv, const float* __restrict__ bv,
    const float* __restrict__ wvd, const float* __restrict__ wvu)
{
    int idx = blockIdx.x * 256 + threadIdx.x;
    if (idx >= NQKV * DM) return;
    int n = idx / DM;
    int d = idx - n * DM;
    int p = n / DM;
    int e = n - p * DM;
    const float *w, *bb, *dn, *up;
    if (p == 0)      { w = wq; bb = bq; dn = wqd; up = wqu; }
    else if (p == 1) { w = wk; bb = bk; dn = wkd; up = wku; }
    else             { w = wv; bb = bv; dn = wvd; up = wvu; }
    float acc = 0.f;
#pragma unroll
    for (int r = 0; r < RANK; r++)
        acc += up[e * RANK + r] * dn[r * DM + d];
    g_Wcat[idx] = w[e * DM + d] + LORA_SCALE * acc;
    if (d == 0) g_bcat[n] = bb[e];
}

// ---------------- kernel 2: QKV GEMM, plain tf32 ----------------
// C[m,n] = x[m,:] . Wcat[n,:] + bcat[n], scattered to g_qkv[p][h][s][dk]
// BM=64, BN=64, BK=16, 128 threads, warp tile 32x32.
__global__ __launch_bounds__(128) void gemm_qkv_tc(const float* __restrict__ x)
{
    __shared__ float Ah[64][20], Bh[64][20];

    const int n0 = blockIdx.x * 64;
    const int m0 = blockIdx.y * 64;
    const int tid = threadIdx.x;
    const int w   = tid >> 5;
    const int lane = tid & 31;
    const int g   = lane >> 2;
    const int tg  = lane & 3;
    const int wm = (w & 1) * 32;
    const int wn = (w >> 1) * 32;

    float acc[2][4][4];
#pragma unroll
    for (int mt = 0; mt < 2; mt++)
#pragma unroll
        for (int nt = 0; nt < 4; nt++)
#pragma unroll
            for (int i = 0; i < 4; i++) acc[mt][nt][i] = 0.f;

    for (int k0 = 0; k0 < DM; k0 += 16) {
#pragma unroll
        for (int i = 0; i < 2; i++) {
            int id = tid + 128 * i;
            int row = id >> 2;
            int c4  = (id & 3) * 4;
            float4 a4 = *(const float4*)(x + (size_t)(m0 + row) * DM + k0 + c4);
            float4 b4 = *(const float4*)(g_Wcat + (size_t)(n0 + row) * DM + k0 + c4);
            float4 ah, bh;
            ah.x = __uint_as_float(f2tf32(a4.x)); ah.y = __uint_as_float(f2tf32(a4.y));
            ah.z = __uint_as_float(f2tf32(a4.z)); ah.w = __uint_as_float(f2tf32(a4.w));
            bh.x = __uint_as_float(f2tf32(b4.x)); bh.y = __uint_as_float(f2tf32(b4.y));
            bh.z = __uint_as_float(f2tf32(b4.z)); bh.w = __uint_as_float(f2tf32(b4.w));
            *(float4*)&Ah[row][c4] = ah;
            *(float4*)&Bh[row][c4] = bh;
        }
        __syncthreads();

#pragma unroll
        for (int ks = 0; ks < 2; ks++) {
            const int kc = 8 * ks;
            uint32_t afh[2][4];
#pragma unroll
            for (int mt = 0; mt < 2; mt++) {
                int r = wm + 16 * mt;
                afh[mt][0] = ldu(&Ah[r + g][kc + tg]);
                afh[mt][1] = ldu(&Ah[r + g + 8][kc + tg]);
                afh[mt][2] = ldu(&Ah[r + g][kc + tg + 4]);
                afh[mt][3] = ldu(&Ah[r + g + 8][kc + tg + 4]);
            }
            uint32_t bfh[4][2];
#pragma unroll
            for (int nt = 0; nt < 4; nt++) {
                int r = wn + 8 * nt + g;
                bfh[nt][0] = ldu(&Bh[r][kc + tg]);
                bfh[nt][1] = ldu(&Bh[r][kc + tg + 4]);
            }
#pragma unroll
            for (int mt = 0; mt < 2; mt++)
#pragma unroll
                for (int nt = 0; nt < 4; nt++)
                    mma_tf32(acc[mt][nt], afh[mt], bfh[nt][0], bfh[nt][1]);
        }
        __syncthreads();
    }

    // epilogue: scatter
#pragma unroll
    for (int mt = 0; mt < 2; mt++)
#pragma unroll
        for (int nt = 0; nt < 4; nt++) {
            int rowA = m0 + wm + 16 * mt + g;
            int colA = n0 + wn + 8 * nt + 2 * tg;
#pragma unroll
            for (int half = 0; half < 2; half++) {
                int mrow = rowA + half * 8;
#pragma unroll
                for (int j = 0; j < 2; j++) {
                    int n = colA + j;
                    int p = n / DM;
                    int rem = n - p * DM;
                    int h = rem >> 6;
                    int dd = rem & 63;
                    g_qkv[(((size_t)p * NH + h) * SEQ + mrow) * DK + dd] =
                        acc[mt][nt][half * 2 + j] + g_bcat[n];
                }
            }
        }
}

// ---------------- kernel 3: flash attention, tf32 tensor cores ----------------
// block: 128 threads (4 warps), 64 q-rows (16 per warp). Key tiles of 32.
__global__ __launch_bounds__(128) void flash_tc()
{
    __shared__ float Ks[32][68];
    __shared__ float Vs[32][72];
    __shared__ float Ps[64][36];

    const int h  = blockIdx.y;
    const int m0 = blockIdx.x * 64;
    const int tid = threadIdx.x;
    const int w = tid >> 5;
    const int lane = tid & 31;
    const int g  = lane >> 2;
    const int tg = lane & 3;

    const float* Qp = g_qkv + (size_t)h * SEQ * DK;
    const float* Kp = g_qkv + (size_t)(NH + h) * SEQ * DK;
    const float* Vp = g_qkv + (size_t)(2 * NH + h) * SEQ * DK;

    const int r0 = m0 + 16 * w + g;      // warp-local rows r0, r0+8

    // Q fragments (scaled by 1/sqrt(dk)), 8 k-subchunks
    uint32_t qa[8][4];
#pragma unroll
    for (int ks = 0; ks < 8; ks++) {
        int c = 8 * ks + tg;
        qa[ks][0] = f2tf32(Qp[(size_t)r0 * DK + c] * INV_SQRT_DK);
        qa[ks][1] = f2tf32(Qp[(size_t)(r0 + 8) * DK + c] * INV_SQRT_DK);
        qa[ks][2] = f2tf32(Qp[(size_t)r0 * DK + c + 4] * INV_SQRT_DK);
        qa[ks][3] = f2tf32(Qp[(size_t)(r0 + 8) * DK + c + 4] * INV_SQRT_DK);
    }

    float oacc[8][4];
#pragma unroll
    for (int dt = 0; dt < 8; dt++)
#pragma unroll
        for (int i = 0; i < 4; i++) oacc[dt][i] = 0.f;
    float m0_ = -1e30f, m1_ = -1e30f, l0 = 0.f, l1 = 0.f;

    for (int kb = 0; kb < SEQ; kb += 32) {
        // cooperative load K, V (tf32)
#pragma unroll
        for (int i = 0; i < 4; i++) {
            int id = tid + 128 * i;          // 512 float4s
            int row = id >> 4;
            int c4  = (id & 15) * 4;
            float4 kv = *(const float4*)(Kp + (size_t)(kb + row) * DK + c4);
            float4 vv = *(const float4*)(Vp + (size_t)(kb + row) * DK + c4);
            float4 kt, vt;
            kt.x = __uint_as_float(f2tf32(kv.x)); kt.y = __uint_as_float(f2tf32(kv.y));
            kt.z = __uint_as_float(f2tf32(kv.z)); kt.w = __uint_as_float(f2tf32(kv.w));
            vt.x = __uint_as_float(f2tf32(vv.x)); vt.y = __uint_as_float(f2tf32(vv.y));
            vt.z = __uint_as_float(f2tf32(vv.z)); vt.w = __uint_as_float(f2tf32(vv.w));
            *(float4*)&Ks[row][c4] = kt;
            *(float4*)&Vs[row][c4] = vt;
        }
        __syncthreads();

        // S = Q . K^T  (64x32 per block; 16x32 per warp)
        float sacc[4][4];
#pragma unroll
        for (int nt = 0; nt < 4; nt++)
#pragma unroll
            for (int i = 0; i < 4; i++) sacc[nt][i] = 0.f;
#pragma unroll
        for (int nt = 0; nt < 4; nt++) {
            int key = 8 * nt + g;
#pragma unroll
            for (int ks = 0; ks < 8; ks++) {
                uint32_t b0 = ldu(&Ks[key][8 * ks + tg]);
                uint32_t b1 = ldu(&Ks[key][8 * ks + tg + 4]);
                mma_tf32(sacc[nt], qa[ks], b0, b1);
            }
        }

        // online softmax (two row groups per lane)
        float tmax0 = -1e30f, tmax1 = -1e30f;
#pragma unroll
        for (int nt = 0; nt < 4; nt++) {
            tmax0 = fmaxf(tmax0, fmaxf(sacc[nt][0], sacc[nt][1]));
            tmax1 = fmaxf(tmax1, fmaxf(sacc[nt][2], sacc[nt][3]));
        }
        tmax0 = fmaxf(tmax0, __shfl_xor_sync(0xffffffff, tmax0, 1));
        tmax0 = fmaxf(tmax0, __shfl_xor_sync(0xffffffff, tmax0, 2));
        tmax1 = fmaxf(tmax1, __shfl_xor_sync(0xffffffff, tmax1, 1));
        tmax1 = fmaxf(tmax1, __shfl_xor_sync(0xffffffff, tmax1, 2));

        float mn0 = fmaxf(m0_, tmax0);
        float mn1 = fmaxf(m1_, tmax1);
        float corr0 = __expf(m0_ - mn0);
        float corr1 = __expf(m1_ - mn1);
        m0_ = mn0; m1_ = mn1;

        float rs0 = 0.f, rs1 = 0.f;
#pragma unroll
        for (int nt = 0; nt < 4; nt++) {
            sacc[nt][0] = __expf(sacc[nt][0] - m0_);
            sacc[nt][1] = __expf(sacc[nt][1] - m0_);
            sacc[nt][2] = __expf(sacc[nt][2] - m1_);
            sacc[nt][3] = __expf(sacc[nt][3] - m1_);
            rs0 += sacc[nt][0] + sacc[nt][1];
            rs1 += sacc[nt][2] + sacc[nt][3];
        }
        rs0 += __shfl_xor_sync(0xffffffff, rs0, 1);
        rs0 += __shfl_xor_sync(0xffffffff, rs0, 2);
        rs1 += __shfl_xor_sync(0xffffffff, rs1, 1);
        rs1 += __shfl_xor_sync(0xffffffff, rs1, 2);
        l0 = l0 * corr0 + rs0;
        l1 = l1 * corr1 + rs1;

        // rescale O
#pragma unroll
        for (int dt = 0; dt < 8; dt++) {
            oacc[dt][0] *= corr0; oacc[dt][1] *= corr0;
            oacc[dt][2] *= corr1; oacc[dt][3] *= corr1;
        }

        // write P (tf32) to smem (warp-private rows)
        {
            int pr = 16 * w + g;
#pragma unroll
            for (int nt = 0; nt < 4; nt++) {
                int pc = 8 * nt + 2 * tg;
                float2 p01, p23;
                p01.x = __uint_as_float(f2tf32(sacc[nt][0]));
                p01.y = __uint_as_float(f2tf32(sacc[nt][1]));
                p23.x = __uint_as_float(f2tf32(sacc[nt][2]));
                p23.y = __uint_as_float(f2tf32(sacc[nt][3]));
                *(float2*)&Ps[pr][pc]     = p01;
                *(float2*)&Ps[pr + 8][pc] = p23;
            }
        }
        __syncwarp();

        // O += P . V
#pragma unroll
        for (int ks = 0; ks < 4; ks++) {
            int pr = 16 * w;
            uint32_t pa[4];
            pa[0] = ldu(&Ps[pr + g][8 * ks + tg]);
            pa[1] = ldu(&Ps[pr + g + 8][8 * ks + tg]);
            pa[2] = ldu(&Ps[pr + g][8 * ks + tg + 4]);
            pa[3] = ldu(&Ps[pr + g + 8][8 * ks + tg + 4]);
#pragma unroll
            for (int dt = 0; dt < 8; dt++) {
                int d = 8 * dt + g;
                uint32_t b0 = ldu(&Vs[8 * ks + tg][d]);
                uint32_t b1 = ldu(&Vs[8 * ks + tg + 4][d]);
                mma_tf32(oacc[dt], pa, b0, b1);
            }
        }
        __syncthreads();
    }

    // epilogue
    float inv0 = 1.f / l0;
    float inv1 = 1.f / l1;
    float* Op = g_attn + (size_t)h * SEQ * DK;
#pragma unroll
    for (int dt = 0; dt < 8; dt++) {
        int c = 8 * dt + 2 * tg;
        float2 v01, v23;
        v01.x = oacc[dt][0] * inv0; v01.y = oacc[dt][1] * inv0;
        v23.x = oacc[dt][2] * inv1; v23.y = oacc[dt][3] * inv1;
        *(float2*)(Op + (size_t)r0 * DK + c)       = v01;
        *(float2*)(Op + (size_t)(r0 + 8) * DK + c) = v23;
    }
}

// ---------------- kernel 4: output projection, plain tf32 ----------------
__global__ __launch_bounds__(128) void gemm_out_tc(
    const float* __restrict__ wo, const float* __restrict__ bo,
    float* __restrict__ out)
{
    __shared__ float Ah[64][20], Bh[64][20];

    const int n0 = blockIdx.x * 64;
    const int m0 = blockIdx.y * 64;
    const int tid = threadIdx.x;
    const int w   = tid >> 5;
    const int lane = tid & 31;
    const int g   = lane >> 2;
    const int tg  = lane & 3;
    const int wm = (w & 1) * 32;
    const int wn = (w >> 1) * 32;

    float acc[2][4][4];
#pragma unroll
    for (int mt = 0; mt < 2; mt++)
#pragma unroll
        for (int nt = 0; nt < 4; nt++)
#pragma unroll
            for (int i = 0; i < 4; i++) acc[mt][nt][i] = 0.f;

    for (int k0 = 0; k0 < DM; k0 += 16) {
#pragma unroll
        for (int i = 0; i < 2; i++) {
            int id = tid + 128 * i;
            int row = id >> 2;
            int c4  = (id & 3) * 4;
            int c = k0 + c4;
            int hh = c >> 6;
            int off = c & 63;
            float4 a4 = *(const float4*)(g_attn + ((size_t)hh * SEQ + (m0 + row)) * DK + off);
            float4 b4 = *(const float4*)(wo + (size_t)(n0 + row) * DM + c);
            float4 ah, bh;
            ah.x = __uint_as_float(f2tf32(a4.x)); ah.y = __uint_as_float(f2tf32(a4.y));
            ah.z = __uint_as_float(f2tf32(a4.z)); ah.w = __uint_as_float(f2tf32(a4.w));
            bh.x = __uint_as_float(f2tf32(b4.x)); bh.y = __uint_as_float(f2tf32(b4.y));
            bh.z = __uint_as_float(f2tf32(b4.z)); bh.w = __uint_as_float(f2tf32(b4.w));
            *(float4*)&Ah[row][c4] = ah;
            *(float4*)&Bh[row][c4] = bh;
        }
        __syncthreads();

#pragma unroll
        for (int ks = 0; ks < 2; ks++) {
            const int kc = 8 * ks;
            uint32_t afh[2][4];
#pragma unroll
            for (int mt = 0; mt < 2; mt++) {
                int r = wm + 16 * mt;
                afh[mt][0] = ldu(&Ah[r + g][kc + tg]);
                afh[mt][1] = ldu(&Ah[r + g + 8][kc + tg]);
                afh[mt][2] = ldu(&Ah[r + g][kc + tg + 4]);
                afh[mt][3] = ldu(&Ah[r + g + 8][kc + tg + 4]);
            }
            uint32_t bfh[4][2];
#pragma unroll
            for (int nt = 0; nt < 4; nt++) {
                int r = wn + 8 * nt + g;
                bfh[nt][0] = ldu(&Bh[r][kc + tg]);
                bfh[nt][1] = ldu(&Bh[r][kc + tg + 4]);
            }
#pragma unroll
            for (int mt = 0; mt < 2; mt++)
#pragma unroll
                for (int nt = 0; nt < 4; nt++)
                    mma_tf32(acc[mt][nt], afh[mt], bfh[nt][0], bfh[nt][1]);
        }
        __syncthreads();
    }

#pragma unroll
    for (int mt = 0; mt < 2; mt++)
#pragma unroll
        for (int nt = 0; nt < 4; nt++) {
            int rowA = m0 + wm + 16 * mt + g;
            int colA = n0 + wn + 8 * nt + 2 * tg;
#pragma unroll
            for (int half = 0; half < 2; half++) {
                int mrow = rowA + half * 8;
                out[(size_t)mrow * DM + colA]     = acc[mt][nt][half * 2]     + bo[colA];
                out[(size_t)mrow * DM + colA + 1] = acc[mt][nt][half * 2 + 1] + bo[colA + 1];
            }
        }
}

// ---------------- launch ----------------
extern "C" void kernel_launch(void* const* d_in, const int* in_sizes, int n_in,
                              void* d_out, int out_size)
{
    const float* x   = (const float*)d_in[0];
    const float* wq  = (const float*)d_in[1];
    const float* bq  = (const float*)d_in[2];
    const float* wk  = (const float*)d_in[3];
    const float* bk  = (const float*)d_in[4];
    const float* wv  = (const float*)d_in[5];
    const float* bv  = (const float*)d_in[6];
    const float* wo  = (const float*)d_in[7];
    const float* bo  = (const float*)d_in[8];
    const float* wqd = (const float*)d_in[9];
    const float* wqu = (const float*)d_in[10];
    const float* wkd = (const float*)d_in[11];
    const float* wku = (const float*)d_in[12];
    const float* wvd = (const float*)d_in[13];
    const float* wvu = (const float*)d_in[14];
    float* out = (float*)d_out;

    {
        int total = NQKV * DM;
        fuse_weights_kernel<<<(total + 255) / 256, 256>>>(
            wq, bq, wqd, wqu, wk, bk, wkd, wku, wv, bv, wvd, wvu);
    }
    {
        dim3 grid(NQKV / 64, SEQ / 64);
        gemm_qkv_tc<<<grid, 128>>>(x);
    }
    {
        dim3 grid(SEQ / 64, NH);
        flash_tc<<<grid, 128>>>();
    }
    {
        dim3 grid(DM / 64, SEQ / 64);
        gemm_out_tc<<<grid, 128>>>(wo, bo, out);
    }
}

// round 8
// speedup vs baseline: 3.6700x; 1.0250x over previous
#include <cuda_runtime.h>
#include <cuda_bf16.h>
#include <math.h>
#include <stdint.h>

#define SEQ   4096
#define DM    768
#define NH    12
#define DK    64
#define RANK  8
#define NQKV  (3*DM)
#define LORA_SCALE 2.0f
#define INV_SQRT_DK 0.125f

// ---------------- scratch ----------------
__device__ float g_Wcat[NQKV * DM];
__device__ float g_bcat[NQKV];
__device__ float g_qkv[3 * NH * SEQ * DK];   // [p][h][s][dk]
__device__ float g_attn[NH * SEQ * DK];      // [h][s][dk]

// ---------------- helpers ----------------
__device__ __forceinline__ uint32_t f2tf32(float x) {
    uint32_t u;
    asm("cvt.rna.tf32.f32 %0, %1;" : "=r"(u) : "f"(x));
    return u;
}

__device__ __forceinline__ void mma_tf32(float* d, const uint32_t* a, uint32_t b0, uint32_t b1) {
    asm volatile(
        "mma.sync.aligned.m16n8k8.row.col.f32.tf32.tf32.f32 "
        "{%0,%1,%2,%3}, {%4,%5,%6,%7}, {%8,%9}, {%0,%1,%2,%3};"
        : "+f"(d[0]), "+f"(d[1]), "+f"(d[2]), "+f"(d[3])
        : "r"(a[0]), "r"(a[1]), "r"(a[2]), "r"(a[3]), "r"(b0), "r"(b1));
}

__device__ __forceinline__ uint32_t ldu(const float* p) { return __float_as_uint(*p); }

// ---------------- kernel 1: fold LoRA ----------------
__global__ __launch_bounds__(256) void fuse_weights_kernel(
    const float* __restrict__ wq, const float* __restrict__ bq,
    const float* __restrict__ wqd, const float* __restrict__ wqu,
    const float* __restrict__ wk, const float* __restrict__ bk,
    const float* __restrict__ wkd, const float* __restrict__ wku,
    const float* __restrict__ wv, const float* __restrict__ bv,
    const float* __restrict__ wvd, const float* __restrict__ wvu)
{
    int idx = blockIdx.x * 256 + threadIdx.x;
    if (idx >= NQKV * DM) return;
    int n = idx / DM;
    int d = idx - n * DM;
    int p = n / DM;
    int e = n - p * DM;
    const float *w, *bb, *dn, *up;
    if (p == 0)      { w = wq; bb = bq; dn = wqd; up = wqu; }
    else if (p == 1) { w = wk; bb = bk; dn = wkd; up = wku; }
    else             { w = wv; bb = bv; dn = wvd; up = wvu; }
    float acc = 0.f;
#pragma unroll
    for (int r = 0; r < RANK; r++)
        acc += up[e * RANK + r] * dn[r * DM + d];
    g_Wcat[idx] = w[e * DM + d] + LORA_SCALE * acc;
    if (d == 0) g_bcat[n] = bb[e];
}

// ---------------- kernel 2: QKV GEMM, plain tf32 ----------------
// C[m,n] = x[m,:] . Wcat[n,:] + bcat[n], scattered to g_qkv[p][h][s][dk]
// Block tile M=64 N=128, BK=16, 128 threads, warp tile 32x64.
__global__ __launch_bounds__(128) void gemm_qkv_tc(const float* __restrict__ x)
{
    __shared__ float Ah[64][20], Bh[128][20];

    const int n0 = blockIdx.x * 128;
    const int m0 = blockIdx.y * 64;
    const int tid = threadIdx.x;
    const int w   = tid >> 5;
    const int lane = tid & 31;
    const int g   = lane >> 2;
    const int tg  = lane & 3;
    const int wm = (w & 1) * 32;
    const int wn = (w >> 1) * 64;

    float acc[2][8][4];
#pragma unroll
    for (int mt = 0; mt < 2; mt++)
#pragma unroll
        for (int nt = 0; nt < 8; nt++)
#pragma unroll
            for (int i = 0; i < 4; i++) acc[mt][nt][i] = 0.f;

    for (int k0 = 0; k0 < DM; k0 += 16) {
#pragma unroll
        for (int i = 0; i < 2; i++) {
            int id = tid + 128 * i;                 // 256 float4 for A
            int row = id >> 2;
            int c4  = (id & 3) * 4;
            float4 a4 = *(const float4*)(x + (size_t)(m0 + row) * DM + k0 + c4);
            float4 ah;
            ah.x = __uint_as_float(f2tf32(a4.x)); ah.y = __uint_as_float(f2tf32(a4.y));
            ah.z = __uint_as_float(f2tf32(a4.z)); ah.w = __uint_as_float(f2tf32(a4.w));
            *(float4*)&Ah[row][c4] = ah;
        }
#pragma unroll
        for (int i = 0; i < 4; i++) {
            int id = tid + 128 * i;                 // 512 float4 for B
            int row = id >> 2;
            int c4  = (id & 3) * 4;
            float4 b4 = *(const float4*)(g_Wcat + (size_t)(n0 + row) * DM + k0 + c4);
            float4 bh;
            bh.x = __uint_as_float(f2tf32(b4.x)); bh.y = __uint_as_float(f2tf32(b4.y));
            bh.z = __uint_as_float(f2tf32(b4.z)); bh.w = __uint_as_float(f2tf32(b4.w));
            *(float4*)&Bh[row][c4] = bh;
        }
        __syncthreads();

#pragma unroll
        for (int ks = 0; ks < 2; ks++) {
            const int kc = 8 * ks;
            uint32_t afh[2][4];
#pragma unroll
            for (int mt = 0; mt < 2; mt++) {
                int r = wm + 16 * mt;
                afh[mt][0] = ldu(&Ah[r + g][kc + tg]);
                afh[mt][1] = ldu(&Ah[r + g + 8][kc + tg]);
                afh[mt][2] = ldu(&Ah[r + g][kc + tg + 4]);
                afh[mt][3] = ldu(&Ah[r + g + 8][kc + tg + 4]);
            }
            uint32_t bfh[8][2];
#pragma unroll
            for (int nt = 0; nt < 8; nt++) {
                int r = wn + 8 * nt + g;
                bfh[nt][0] = ldu(&Bh[r][kc + tg]);
                bfh[nt][1] = ldu(&Bh[r][kc + tg + 4]);
            }
#pragma unroll
            for (int mt = 0; mt < 2; mt++)
#pragma unroll
                for (int nt = 0; nt < 8; nt++)
                    mma_tf32(acc[mt][nt], afh[mt], bfh[nt][0], bfh[nt][1]);
        }
        __syncthreads();
    }

    // epilogue: scatter
#pragma unroll
    for (int mt = 0; mt < 2; mt++)
#pragma unroll
        for (int nt = 0; nt < 8; nt++) {
            int rowA = m0 + wm + 16 * mt + g;
            int colA = n0 + wn + 8 * nt + 2 * tg;
#pragma unroll
            for (int half = 0; half < 2; half++) {
                int mrow = rowA + half * 8;
#pragma unroll
                for (int j = 0; j < 2; j++) {
                    int n = colA + j;
                    int p = n / DM;
                    int rem = n - p * DM;
                    int h = rem >> 6;
                    int dd = rem & 63;
                    g_qkv[(((size_t)p * NH + h) * SEQ + mrow) * DK + dd] =
                        acc[mt][nt][half * 2 + j] + g_bcat[n];
                }
            }
        }
}

// ---------------- kernel 3: flash attention ----------------
// 64 threads (2 warps), each warp 32 q-rows (2 m-subtiles), key tiles of 32.
__global__ __launch_bounds__(64, 5) void flash_tc()
{
    __shared__ float Ks[32][68];
    __shared__ float Vs[32][72];
    __shared__ float Ps[64][36];

    const int h  = blockIdx.y;
    const int m0 = blockIdx.x * 64;
    const int tid = threadIdx.x;
    const int w = tid >> 5;
    const int lane = tid & 31;
    const int g  = lane >> 2;
    const int tg = lane & 3;

    const float* Qp = g_qkv + (size_t)h * SEQ * DK;
    const float* Kp = g_qkv + (size_t)(NH + h) * SEQ * DK;
    const float* Vp = g_qkv + (size_t)(2 * NH + h) * SEQ * DK;

    // Q fragments (scaled), 2 m-subtiles x 8 k-chunks
    uint32_t qa[2][8][4];
#pragma unroll
    for (int mt = 0; mt < 2; mt++) {
        int r = m0 + 32 * w + 16 * mt + g;
#pragma unroll
        for (int ks = 0; ks < 8; ks++) {
            int c = 8 * ks + tg;
            qa[mt][ks][0] = f2tf32(Qp[(size_t)r * DK + c] * INV_SQRT_DK);
            qa[mt][ks][1] = f2tf32(Qp[(size_t)(r + 8) * DK + c] * INV_SQRT_DK);
            qa[mt][ks][2] = f2tf32(Qp[(size_t)r * DK + c + 4] * INV_SQRT_DK);
            qa[mt][ks][3] = f2tf32(Qp[(size_t)(r + 8) * DK + c + 4] * INV_SQRT_DK);
        }
    }

    float oacc[2][8][4];
#pragma unroll
    for (int mt = 0; mt < 2; mt++)
#pragma unroll
        for (int dt = 0; dt < 8; dt++)
#pragma unroll
            for (int i = 0; i < 4; i++) oacc[mt][dt][i] = 0.f;
    float m_[2][2] = {{-1e30f, -1e30f}, {-1e30f, -1e30f}};
    float l_[2][2] = {{0.f, 0.f}, {0.f, 0.f}};

    for (int kb = 0; kb < SEQ; kb += 32) {
        // cooperative load K, V (tf32): 512 float4 each, 64 threads -> 8 apiece
#pragma unroll
        for (int i = 0; i < 8; i++) {
            int id = tid + 64 * i;
            int row = id >> 4;
            int c4  = (id & 15) * 4;
            float4 kv = *(const float4*)(Kp + (size_t)(kb + row) * DK + c4);
            float4 vv = *(const float4*)(Vp + (size_t)(kb + row) * DK + c4);
            float4 kt, vt;
            kt.x = __uint_as_float(f2tf32(kv.x)); kt.y = __uint_as_float(f2tf32(kv.y));
            kt.z = __uint_as_float(f2tf32(kv.z)); kt.w = __uint_as_float(f2tf32(kv.w));
            vt.x = __uint_as_float(f2tf32(vv.x)); vt.y = __uint_as_float(f2tf32(vv.y));
            vt.z = __uint_as_float(f2tf32(vv.z)); vt.w = __uint_as_float(f2tf32(vv.w));
            *(float4*)&Ks[row][c4] = kt;
            *(float4*)&Vs[row][c4] = vt;
        }
        __syncthreads();

        // S = Q . K^T  (32 rows x 32 keys per warp)
        float sacc[2][4][4];
#pragma unroll
        for (int mt = 0; mt < 2; mt++)
#pragma unroll
            for (int nt = 0; nt < 4; nt++)
#pragma unroll
                for (int i = 0; i < 4; i++) sacc[mt][nt][i] = 0.f;
#pragma unroll
        for (int nt = 0; nt < 4; nt++) {
            int key = 8 * nt + g;
#pragma unroll
            for (int ks = 0; ks < 8; ks++) {
                uint32_t b0 = ldu(&Ks[key][8 * ks + tg]);
                uint32_t b1 = ldu(&Ks[key][8 * ks + tg + 4]);
                mma_tf32(sacc[0][nt], qa[0][ks], b0, b1);
                mma_tf32(sacc[1][nt], qa[1][ks], b0, b1);
            }
        }

        // online softmax per m-subtile
#pragma unroll
        for (int mt = 0; mt < 2; mt++) {
            float tmax0 = -1e30f, tmax1 = -1e30f;
#pragma unroll
            for (int nt = 0; nt < 4; nt++) {
                tmax0 = fmaxf(tmax0, fmaxf(sacc[mt][nt][0], sacc[mt][nt][1]));
                tmax1 = fmaxf(tmax1, fmaxf(sacc[mt][nt][2], sacc[mt][nt][3]));
            }
            tmax0 = fmaxf(tmax0, __shfl_xor_sync(0xffffffff, tmax0, 1));
            tmax0 = fmaxf(tmax0, __shfl_xor_sync(0xffffffff, tmax0, 2));
            tmax1 = fmaxf(tmax1, __shfl_xor_sync(0xffffffff, tmax1, 1));
            tmax1 = fmaxf(tmax1, __shfl_xor_sync(0xffffffff, tmax1, 2));

            float mn0 = fmaxf(m_[mt][0], tmax0);
            float mn1 = fmaxf(m_[mt][1], tmax1);
            float corr0 = __expf(m_[mt][0] - mn0);
            float corr1 = __expf(m_[mt][1] - mn1);
            m_[mt][0] = mn0; m_[mt][1] = mn1;

            float rs0 = 0.f, rs1 = 0.f;
#pragma unroll
            for (int nt = 0; nt < 4; nt++) {
                sacc[mt][nt][0] = __expf(sacc[mt][nt][0] - mn0);
                sacc[mt][nt][1] = __expf(sacc[mt][nt][1] - mn0);
                sacc[mt][nt][2] = __expf(sacc[mt][nt][2] - mn1);
                sacc[mt][nt][3] = __expf(sacc[mt][nt][3] - mn1);
                rs0 += sacc[mt][nt][0] + sacc[mt][nt][1];
                rs1 += sacc[mt][nt][2] + sacc[mt][nt][3];
            }
            rs0 += __shfl_xor_sync(0xffffffff, rs0, 1);
            rs0 += __shfl_xor_sync(0xffffffff, rs0, 2);
            rs1 += __shfl_xor_sync(0xffffffff, rs1, 1);
            rs1 += __shfl_xor_sync(0xffffffff, rs1, 2);
            l_[mt][0] = l_[mt][0] * corr0 + rs0;
            l_[mt][1] = l_[mt][1] * corr1 + rs1;

#pragma unroll
            for (int dt = 0; dt < 8; dt++) {
                oacc[mt][dt][0] *= corr0; oacc[mt][dt][1] *= corr0;
                oacc[mt][dt][2] *= corr1; oacc[mt][dt][3] *= corr1;
            }

            // write P (tf32) into warp-private rows of Ps
            int pr = 32 * w + 16 * mt + g;
#pragma unroll
            for (int nt = 0; nt < 4; nt++) {
                int pc = 8 * nt + 2 * tg;
                float2 p01, p23;
                p01.x = __uint_as_float(f2tf32(sacc[mt][nt][0]));
                p01.y = __uint_as_float(f2tf32(sacc[mt][nt][1]));
                p23.x = __uint_as_float(f2tf32(sacc[mt][nt][2]));
                p23.y = __uint_as_float(f2tf32(sacc[mt][nt][3]));
                *(float2*)&Ps[pr][pc]     = p01;
                *(float2*)&Ps[pr + 8][pc] = p23;
            }
        }
        __syncwarp();

        // O += P . V
#pragma unroll
        for (int ks = 0; ks < 4; ks++) {
            uint32_t pa0[4], pa1[4];
            int b0r = 32 * w;
            pa0[0] = ldu(&Ps[b0r + g][8 * ks + tg]);
            pa0[1] = ldu(&Ps[b0r + g + 8][8 * ks + tg]);
            pa0[2] = ldu(&Ps[b0r + g][8 * ks + tg + 4]);
            pa0[3] = ldu(&Ps[b0r + g + 8][8 * ks + tg + 4]);
            pa1[0] = ldu(&Ps[b0r + 16 + g][8 * ks + tg]);
            pa1[1] = ldu(&Ps[b0r + 24 + g][8 * ks + tg]);
            pa1[2] = ldu(&Ps[b0r + 16 + g][8 * ks + tg + 4]);
            pa1[3] = ldu(&Ps[b0r + 24 + g][8 * ks + tg + 4]);
#pragma unroll
            for (int dt = 0; dt < 8; dt++) {
                int d = 8 * dt + g;
                uint32_t b0 = ldu(&Vs[8 * ks + tg][d]);
                uint32_t b1 = ldu(&Vs[8 * ks + tg + 4][d]);
                mma_tf32(oacc[0][dt], pa0, b0, b1);
                mma_tf32(oacc[1][dt], pa1, b0, b1);
            }
        }
        __syncthreads();
    }

    // epilogue
    float* Op = g_attn + (size_t)h * SEQ * DK;
#pragma unroll
    for (int mt = 0; mt < 2; mt++) {
        float inv0 = 1.f / l_[mt][0];
        float inv1 = 1.f / l_[mt][1];
        int rr = m0 + 32 * w + 16 * mt + g;
#pragma unroll
        for (int dt = 0; dt < 8; dt++) {
            int c = 8 * dt + 2 * tg;
            float2 v01, v23;
            v01.x = oacc[mt][dt][0] * inv0; v01.y = oacc[mt][dt][1] * inv0;
            v23.x = oacc[mt][dt][2] * inv1; v23.y = oacc[mt][dt][3] * inv1;
            *(float2*)(Op + (size_t)rr * DK + c)       = v01;
            *(float2*)(Op + (size_t)(rr + 8) * DK + c) = v23;
        }
    }
}

// ---------------- kernel 4: output projection, plain tf32 ----------------
// Block tile M=64 N=128, BK=16, 128 threads, warp tile 32x64.
__global__ __launch_bounds__(128) void gemm_out_tc(
    const float* __restrict__ wo, const float* __restrict__ bo,
    float* __restrict__ out)
{
    __shared__ float Ah[64][20], Bh[128][20];

    const int n0 = blockIdx.x * 128;
    const int m0 = blockIdx.y * 64;
    const int tid = threadIdx.x;
    const int w   = tid >> 5;
    const int lane = tid & 31;
    const int g   = lane >> 2;
    const int tg  = lane & 3;
    const int wm = (w & 1) * 32;
    const int wn = (w >> 1) * 64;

    float acc[2][8][4];
#pragma unroll
    for (int mt = 0; mt < 2; mt++)
#pragma unroll
        for (int nt = 0; nt < 8; nt++)
#pragma unroll
            for (int i = 0; i < 4; i++) acc[mt][nt][i] = 0.f;

    for (int k0 = 0; k0 < DM; k0 += 16) {
#pragma unroll
        for (int i = 0; i < 2; i++) {
            int id = tid + 128 * i;
            int row = id >> 2;
            int c4  = (id & 3) * 4;
            int c = k0 + c4;
            int hh = c >> 6;
            int off = c & 63;
            float4 a4 = *(const float4*)(g_attn + ((size_t)hh * SEQ + (m0 + row)) * DK + off);
            float4 ah;
            ah.x = __uint_as_float(f2tf32(a4.x)); ah.y = __uint_as_float(f2tf32(a4.y));
            ah.z = __uint_as_float(f2tf32(a4.z)); ah.w = __uint_as_float(f2tf32(a4.w));
            *(float4*)&Ah[row][c4] = ah;
        }
#pragma unroll
        for (int i = 0; i < 4; i++) {
            int id = tid + 128 * i;
            int row = id >> 2;
            int c4  = (id & 3) * 4;
            float4 b4 = *(const float4*)(wo + (size_t)(n0 + row) * DM + k0 + c4);
            float4 bh;
            bh.x = __uint_as_float(f2tf32(b4.x)); bh.y = __uint_as_float(f2tf32(b4.y));
            bh.z = __uint_as_float(f2tf32(b4.z)); bh.w = __uint_as_float(f2tf32(b4.w));
            *(float4*)&Bh[row][c4] = bh;
        }
        __syncthreads();

#pragma unroll
        for (int ks = 0; ks < 2; ks++) {
            const int kc = 8 * ks;
            uint32_t afh[2][4];
#pragma unroll
            for (int mt = 0; mt < 2; mt++) {
                int r = wm + 16 * mt;
                afh[mt][0] = ldu(&Ah[r + g][kc + tg]);
                afh[mt][1] = ldu(&Ah[r + g + 8][kc + tg]);
                afh[mt][2] = ldu(&Ah[r + g][kc + tg + 4]);
                afh[mt][3] = ldu(&Ah[r + g + 8][kc + tg + 4]);
            }
            uint32_t bfh[8][2];
#pragma unroll
            for (int nt = 0; nt < 8; nt++) {
                int r = wn + 8 * nt + g;
                bfh[nt][0] = ldu(&Bh[r][kc + tg]);
                bfh[nt][1] = ldu(&Bh[r][kc + tg + 4]);
            }
#pragma unroll
            for (int mt = 0; mt < 2; mt++)
#pragma unroll
                for (int nt = 0; nt < 8; nt++)
                    mma_tf32(acc[mt][nt], afh[mt], bfh[nt][0], bfh[nt][1]);
        }
        __syncthreads();
    }

#pragma unroll
    for (int mt = 0; mt < 2; mt++)
#pragma unroll
        for (int nt = 0; nt < 8; nt++) {
            int rowA = m0 + wm + 16 * mt + g;
            int colA = n0 + wn + 8 * nt + 2 * tg;
#pragma unroll
            for (int half = 0; half < 2; half++) {
                int mrow = rowA + half * 8;
                out[(size_t)mrow * DM + colA]     = acc[mt][nt][half * 2]     + bo[colA];
                out[(size_t)mrow * DM + colA + 1] = acc[mt][nt][half * 2 + 1] + bo[colA + 1];
            }
        }
}

// ---------------- launch ----------------
extern "C" void kernel_launch(void* const* d_in, const int* in_sizes, int n_in,
                              void* d_out, int out_size)
{
    const float* x   = (const float*)d_in[0];
    const float* wq  = (const float*)d_in[1];
    const float* bq  = (const float*)d_in[2];
    const float* wk  = (const float*)d_in[3];
    const float* bk  = (const float*)d_in[4];
    const float* wv  = (const float*)d_in[5];
    const float* bv  = (const float*)d_in[6];
    const float* wo  = (const float*)d_in[7];
    const float* bo  = (const float*)d_in[8];
    const float* wqd = (const float*)d_in[9];
    const float* wqu = (const float*)d_in[10];
    const float* wkd = (const float*)d_in[11];
    const float* wku = (const float*)d_in[12];
    const float* wvd = (const float*)d_in[13];
    const float* wvu = (const float*)d_in[14];
    float* out = (float*)d_out;

    {
        int total = NQKV * DM;
        fuse_weights_kernel<<<(total + 255) / 256, 256>>>(
            wq, bq, wqd, wqu, wk, bk, wkd, wku, wv, bv, wvd, wvu);
    }
    {
        dim3 grid(NQKV / 128, SEQ / 64);
        gemm_qkv_tc<<<grid, 128>>>(x);
    }
    {
        dim3 grid(SEQ / 64, NH);
        flash_tc<<<grid, 64>>>();
    }
    {
        dim3 grid(DM / 128, SEQ / 64);
        gemm_out_tc<<<grid, 128>>>(wo, bo, out);
    }
}